// round 14
// baseline (speedup 1.0000x reference)
#include <cuda_runtime.h>
#include <cuda_bf16.h>
#include <math.h>
#include <stdint.h>

// Problem constants
#define N_TOK 65536
#define D_IN  1024
#define H_DIM 512
#define HH    256          // H/2
#define R_REG 16
#define M_PER (N_TOK / R_REG)   // 4096
#define SPLITS 64

// ---------------- static device scratch (no allocations allowed) ----------------
// region_emb stored PACKED: uint32 = bf16(hi) | bf16(lo)<<16  (hi+lo ~= fp32 value)
__device__ uint32_t g_reP[N_TOK * H_DIM];                // 128 MiB
__device__ uint2    g_W1P[512 * 512];                    // W1 split planes, [kpair][n]
__device__ uint2    g_WaP[256 * 256];                    // Wa1 split planes, [kpair][n]
__device__ float g_scores[N_TOK];
__device__ float g_rmax[R_REG];
__device__ float g_rsum[R_REG];
__device__ float g_partial[R_REG * SPLITS * H_DIM];      // 2 MiB
__device__ float g_region_features[R_REG * H_DIM];
__device__ float g_slide_emb[R_REG * H_DIM];
__device__ float g_sa[R_REG];

__device__ __forceinline__ float gelu_f(float x) {
    // exact-erf GELU (matches torch nn.GELU default / jax approximate=False)
    return 0.5f * x * (1.0f + erff(x * 0.70710678118654752440f));
}

// pack fp32 -> (bf16 hi | bf16 lo << 16)
__device__ __forceinline__ uint32_t packf(float x) {
    __nv_bfloat16 hb = __float2bfloat16_rn(x);
    float hf = __bfloat162float(hb);
    __nv_bfloat16 lb = __float2bfloat16_rn(x - hf);
    return (uint32_t)(*(uint16_t*)&hb) | ((uint32_t)(*(uint16_t*)&lb) << 16);
}
// unpack to fp32: bf16->fp32 is just a 16-bit left shift of the bit pattern
__device__ __forceinline__ float unpackf(uint32_t u) {
    return __uint_as_float(u << 16) + __uint_as_float(u & 0xFFFF0000u);
}

// ---------------- bf16 split helper (A-side, in-kernel) ----------------
__device__ __forceinline__ void split_bf(float x, uint32_t& h, uint32_t& l) {
    __nv_bfloat16 hb = __float2bfloat16_rn(x);
    float r = x - __bfloat162float(hb);   // exact in fp32
    __nv_bfloat16 lb = __float2bfloat16_rn(r);
    h = (uint32_t)(*(uint16_t*)&hb);
    l = (uint32_t)(*(uint16_t*)&lb);
}

// m16n8k16 bf16 MMA, f32 accumulate (sm_80+ mma.sync — valid on plain sm_103)
__device__ __forceinline__ void mma_bf16(float* d, const uint32_t* a, const uint32_t* b) {
    asm volatile(
        "mma.sync.aligned.m16n8k16.row.col.f32.bf16.bf16.f32 "
        "{%0,%1,%2,%3}, {%4,%5,%6,%7}, {%8,%9}, {%0,%1,%2,%3};"
        : "+f"(d[0]), "+f"(d[1]), "+f"(d[2]), "+f"(d[3])
        : "r"(a[0]), "r"(a[1]), "r"(a[2]), "r"(a[3]), "r"(b[0]), "r"(b[1]));
}

// =================================================================================
// KPREP: split W1 (1024x512) and Wa1 (512x256) into packed k-pair planes.
// g_W1P[kp*512+n] = { pack(W1[2kp][n]), pack(W1[2kp+1][n]) }; same for Wa1.
// =================================================================================
__global__ void kprep(const float* __restrict__ W1, const float* __restrict__ Wa1)
{
    const int i = blockIdx.x * 256 + threadIdx.x;
    if (i < 512 * 512) {
        const int kp = i >> 9, n = i & 511;
        g_W1P[i] = make_uint2(packf(W1[(2 * kp) * 512 + n]),
                              packf(W1[(2 * kp + 1) * 512 + n]));
    } else if (i < 512 * 512 + 256 * 256) {
        const int j = i - 512 * 512;
        const int kp = j >> 8, n = j & 255;
        g_WaP[j] = make_uint2(packf(Wa1[(2 * kp) * 256 + n]),
                              packf(Wa1[(2 * kp + 1) * 256 + n]));
    }
}

// =================================================================================
// K1 (mma.sync bf16-split, double-buffered): region_emb = gelu(E @ W1 + b1)
// CTA tile 128x128, BK=16, 512 threads = 16 warps 4(m)x4(n), warp tile 32x32.
// 2-stage smem, ONE __syncthreads per chunk; global loads overlap MMA phase.
// A planes: 48B row stride (12 words, conflict-free frag LDS).
// B planes: 32B row stride (8 words, 2-way frag conflict — accepted, saves smem).
// B comes pre-split from g_W1P (no in-loop convert); A split in-kernel.
// =================================================================================
#define K1_AH 0
#define K1_AL 6144
#define K1_BH 12288
#define K1_BL 16384
#define K1_STAGE 20480

__global__ __launch_bounds__(512, 1)
void k1_mma(const float* __restrict__ A, const float* __restrict__ bias)
{
    __shared__ __align__(16) unsigned char sm[2 * K1_STAGE];

    const int tid = threadIdx.x;
    const int wid = tid >> 5;
    const int lane = tid & 31;
    const int g = lane >> 2;
    const int t = lane & 3;
    const int bx = blockIdx.x;     // N block 0..3
    const int by = blockIdx.y;     // M block 0..511

    const int warp_m = (wid & 3) * 32;
    const int warp_n = (wid >> 2) * 32;

    // A: 1 float4/thread per chunk
    const int a_row = tid >> 2;
    const int a_q   = tid & 3;
    const float* Ag = A + (long)(by * 128 + a_row) * D_IN + a_q * 4;
    // B: kpair = tid>>6 (0..7), n = (tid&63) + 64*nj
    const int b_kp = tid >> 6;
    const int b_n  = tid & 63;

    float acc[2][4][4];
    #pragma unroll
    for (int mt = 0; mt < 2; mt++)
        #pragma unroll
        for (int nt = 0; nt < 4; nt++)
            #pragma unroll
            for (int r = 0; r < 4; r++) acc[mt][nt][r] = 0.f;

    // ---- prefetch chunk 0 ----
    float4 pa = *(const float4*)Ag;
    uint2 pW0 = g_W1P[(long)b_kp * 512 + bx * 128 + b_n];
    uint2 pW1 = g_W1P[(long)b_kp * 512 + bx * 128 + b_n + 64];

    // ---- store chunk 0 into stage 0 ----
    {
        uint32_t h0, h1, h2, h3, l0, l1, l2, l3;
        split_bf(pa.x, h0, l0); split_bf(pa.y, h1, l1);
        split_bf(pa.z, h2, l2); split_bf(pa.w, h3, l3);
        *(uint2*)(sm + K1_AH + a_row * 48 + a_q * 8) = make_uint2(h0 | (h1 << 16), h2 | (h3 << 16));
        *(uint2*)(sm + K1_AL + a_row * 48 + a_q * 8) = make_uint2(l0 | (l1 << 16), l2 | (l3 << 16));
        *(uint32_t*)(sm + K1_BH + b_n * 32 + b_kp * 4)        = (pW0.x & 0xFFFF) | (pW0.y << 16);
        *(uint32_t*)(sm + K1_BL + b_n * 32 + b_kp * 4)        = (pW0.x >> 16) | (pW0.y & 0xFFFF0000u);
        *(uint32_t*)(sm + K1_BH + (b_n + 64) * 32 + b_kp * 4) = (pW1.x & 0xFFFF) | (pW1.y << 16);
        *(uint32_t*)(sm + K1_BL + (b_n + 64) * 32 + b_kp * 4) = (pW1.x >> 16) | (pW1.y & 0xFFFF0000u);
    }
    __syncthreads();

    for (int c = 0; c < D_IN / 16; c++) {
        // prefetch next chunk (overlaps MMA below)
        if (c + 1 < D_IN / 16) {
            pa = *(const float4*)(Ag + (c + 1) * 16);
            pW0 = g_W1P[(long)((c + 1) * 8 + b_kp) * 512 + bx * 128 + b_n];
            pW1 = g_W1P[(long)((c + 1) * 8 + b_kp) * 512 + bx * 128 + b_n + 64];
        }

        const unsigned char* st = sm + (c & 1) * K1_STAGE;
        const uint32_t* AH = (const uint32_t*)(st + K1_AH);
        const uint32_t* AL = (const uint32_t*)(st + K1_AL);
        const uint32_t* BH = (const uint32_t*)(st + K1_BH);
        const uint32_t* BL = (const uint32_t*)(st + K1_BL);

        uint32_t ah[2][4], al_[2][4];
        #pragma unroll
        for (int mt = 0; mt < 2; mt++) {
            const int r0 = (warp_m + mt * 16 + g) * 12 + t;
            ah[mt][0]  = AH[r0];       ah[mt][1]  = AH[r0 + 96];
            ah[mt][2]  = AH[r0 + 4];   ah[mt][3]  = AH[r0 + 100];
            al_[mt][0] = AL[r0];       al_[mt][1] = AL[r0 + 96];
            al_[mt][2] = AL[r0 + 4];   al_[mt][3] = AL[r0 + 100];
        }
        #pragma unroll
        for (int nt = 0; nt < 4; nt++) {
            const int q0 = (warp_n + nt * 8 + g) * 8 + t;
            uint32_t bh[2], bl[2];
            bh[0] = BH[q0]; bh[1] = BH[q0 + 4];
            bl[0] = BL[q0]; bl[1] = BL[q0 + 4];
            #pragma unroll
            for (int mt = 0; mt < 2; mt++) {
                mma_bf16(acc[mt][nt], ah[mt],  bh);
                mma_bf16(acc[mt][nt], ah[mt],  bl);
                mma_bf16(acc[mt][nt], al_[mt], bh);
            }
        }

        // store next chunk into the other stage
        if (c + 1 < D_IN / 16) {
            unsigned char* sn = sm + ((c + 1) & 1) * K1_STAGE;
            uint32_t h0, h1, h2, h3, l0, l1, l2, l3;
            split_bf(pa.x, h0, l0); split_bf(pa.y, h1, l1);
            split_bf(pa.z, h2, l2); split_bf(pa.w, h3, l3);
            *(uint2*)(sn + K1_AH + a_row * 48 + a_q * 8) = make_uint2(h0 | (h1 << 16), h2 | (h3 << 16));
            *(uint2*)(sn + K1_AL + a_row * 48 + a_q * 8) = make_uint2(l0 | (l1 << 16), l2 | (l3 << 16));
            *(uint32_t*)(sn + K1_BH + b_n * 32 + b_kp * 4)        = (pW0.x & 0xFFFF) | (pW0.y << 16);
            *(uint32_t*)(sn + K1_BL + b_n * 32 + b_kp * 4)        = (pW0.x >> 16) | (pW0.y & 0xFFFF0000u);
            *(uint32_t*)(sn + K1_BH + (b_n + 64) * 32 + b_kp * 4) = (pW1.x & 0xFFFF) | (pW1.y << 16);
            *(uint32_t*)(sn + K1_BL + (b_n + 64) * 32 + b_kp * 4) = (pW1.x >> 16) | (pW1.y & 0xFFFF0000u);
        }
        __syncthreads();
    }

    // ---- epilogue: bias + gelu, packed (hi|lo) uint32 stores ----
    #pragma unroll
    for (int mt = 0; mt < 2; mt++) {
        const int row0 = by * 128 + warp_m + mt * 16 + g;
        #pragma unroll
        for (int nt = 0; nt < 4; nt++) {
            const int col = bx * 128 + warp_n + nt * 8 + 2 * t;
            const float2 bb = *(const float2*)(bias + col);
            const float* d = acc[mt][nt];
            uint2 p0 = make_uint2(packf(gelu_f(d[0] + bb.x)), packf(gelu_f(d[1] + bb.y)));
            uint2 p1 = make_uint2(packf(gelu_f(d[2] + bb.x)), packf(gelu_f(d[3] + bb.y)));
            *(uint2*)(g_reP + (long)row0 * H_DIM + col) = p0;
            *(uint2*)(g_reP + (long)(row0 + 8) * H_DIM + col) = p1;
        }
    }
}

// =================================================================================
// K2 (mma.sync bf16-split): scores = tanh(region_emb @ Wa1 + ba1) @ Wa2 + ba2
// CTA tile 128x256 (full Wa1 width), BK=16, 512 threads 4(m)x4(n), warp 32x64.
// A = packed region_emb planes (from k1), B = packed Wa1 planes (from kprep).
// tanh + Wa2 contraction fused in epilogue, reduced via quad-shfl + smem.
// =================================================================================
#define K2_AH 0
#define K2_AL 6144
#define K2_BH 12288
#define K2_BL 20480
#define K2_SP 28672
#define K2_SMEM 30720

__global__ __launch_bounds__(512, 1)
void k2_mma(const float* __restrict__ ba1, const float* __restrict__ Wa2,
            const float* __restrict__ ba2)
{
    __shared__ __align__(16) unsigned char sm[K2_SMEM];

    const int tid = threadIdx.x;
    const int wid = tid >> 5;
    const int lane = tid & 31;
    const int g = lane >> 2;
    const int t = lane & 3;
    const int blk = blockIdx.x;    // token block 0..511

    const int warp_m = (wid & 3) * 32;
    const int warp_n = (wid >> 2) * 64;

    // A: 1 uint4 (4 packed words = 4 k)/thread per chunk
    const int a_row = tid >> 2;
    const int a_kq  = tid & 3;
    const uint32_t* Arep = g_reP + (long)(blk * 128 + a_row) * H_DIM;
    // B: kpair = tid>>6 (0..7), n = (tid&63) + 64*i
    const int b_kp = tid >> 6;
    const int b_n  = tid & 63;

    float acc[2][8][4];
    #pragma unroll
    for (int mt = 0; mt < 2; mt++)
        #pragma unroll
        for (int nt = 0; nt < 8; nt++)
            #pragma unroll
            for (int r = 0; r < 4; r++) acc[mt][nt][r] = 0.f;

    uint4 pa = *(const uint4*)(Arep + a_kq * 4);
    uint2 pb[4];
    #pragma unroll
    for (int i = 0; i < 4; i++)
        pb[i] = g_WaP[(long)b_kp * 256 + b_n + 64 * i];

    for (int c = 0; c < H_DIM / 16; c++) {
        // ---- store chunk into smem planes ----
        {
            uint32_t p0h = (pa.x & 0xFFFF) | (pa.y << 16);
            uint32_t p0l = (pa.x >> 16) | (pa.y & 0xFFFF0000u);
            uint32_t p1h = (pa.z & 0xFFFF) | (pa.w << 16);
            uint32_t p1l = (pa.z >> 16) | (pa.w & 0xFFFF0000u);
            *(uint2*)(sm + K2_AH + a_row * 48 + a_kq * 8) = make_uint2(p0h, p1h);
            *(uint2*)(sm + K2_AL + a_row * 48 + a_kq * 8) = make_uint2(p0l, p1l);
            #pragma unroll
            for (int i = 0; i < 4; i++) {
                const int n = b_n + 64 * i;
                *(uint32_t*)(sm + K2_BH + n * 32 + b_kp * 4) = (pb[i].x & 0xFFFF) | (pb[i].y << 16);
                *(uint32_t*)(sm + K2_BL + n * 32 + b_kp * 4) = (pb[i].x >> 16) | (pb[i].y & 0xFFFF0000u);
            }
        }
        __syncthreads();

        if (c + 1 < H_DIM / 16) {
            pa = *(const uint4*)(Arep + (c + 1) * 16 + a_kq * 4);
            #pragma unroll
            for (int i = 0; i < 4; i++)
                pb[i] = g_WaP[(long)((c + 1) * 8 + b_kp) * 256 + b_n + 64 * i];
        }

        const uint32_t* AH = (const uint32_t*)(sm + K2_AH);
        const uint32_t* AL = (const uint32_t*)(sm + K2_AL);
        const uint32_t* BH = (const uint32_t*)(sm + K2_BH);
        const uint32_t* BL = (const uint32_t*)(sm + K2_BL);

        uint32_t ah[2][4], al_[2][4];
        #pragma unroll
        for (int mt = 0; mt < 2; mt++) {
            const int r0 = (warp_m + mt * 16 + g) * 12 + t;
            ah[mt][0]  = AH[r0];       ah[mt][1]  = AH[r0 + 96];
            ah[mt][2]  = AH[r0 + 4];   ah[mt][3]  = AH[r0 + 100];
            al_[mt][0] = AL[r0];       al_[mt][1] = AL[r0 + 96];
            al_[mt][2] = AL[r0 + 4];   al_[mt][3] = AL[r0 + 100];
        }
        #pragma unroll
        for (int nt = 0; nt < 8; nt++) {
            const int q0 = (warp_n + nt * 8 + g) * 8 + t;
            uint32_t bh[2], bl[2];
            bh[0] = BH[q0]; bh[1] = BH[q0 + 4];
            bl[0] = BL[q0]; bl[1] = BL[q0 + 4];
            #pragma unroll
            for (int mt = 0; mt < 2; mt++) {
                mma_bf16(acc[mt][nt], ah[mt],  bh);
                mma_bf16(acc[mt][nt], ah[mt],  bl);
                mma_bf16(acc[mt][nt], al_[mt], bh);
            }
        }
        __syncthreads();
    }

    // ---- epilogue: tanh * Wa2 row-contraction, quad-shfl + smem reduce ----
    float* spart = (float*)(sm + K2_SP);   // [4 n-warp groups][128 rows]
    #pragma unroll
    for (int mt = 0; mt < 2; mt++) {
        float s0 = 0.f, s1 = 0.f;
        #pragma unroll
        for (int nt = 0; nt < 8; nt++) {
            const int col = warp_n + nt * 8 + 2 * t;
            const float2 bb = *(const float2*)(ba1 + col);
            const float2 ww = *(const float2*)(Wa2 + col);
            const float* d = acc[mt][nt];
            s0 += tanhf(d[0] + bb.x) * ww.x + tanhf(d[1] + bb.y) * ww.y;
            s1 += tanhf(d[2] + bb.x) * ww.x + tanhf(d[3] + bb.y) * ww.y;
        }
        s0 += __shfl_down_sync(0xffffffffu, s0, 2, 4);
        s0 += __shfl_down_sync(0xffffffffu, s0, 1, 4);
        s1 += __shfl_down_sync(0xffffffffu, s1, 2, 4);
        s1 += __shfl_down_sync(0xffffffffu, s1, 1, 4);
        if (t == 0) {
            spart[(wid >> 2) * 128 + warp_m + mt * 16 + g]     = s0;
            spart[(wid >> 2) * 128 + warp_m + mt * 16 + g + 8] = s1;
        }
    }
    __syncthreads();
    if (tid < 128) {
        const float s = spart[tid] + spart[128 + tid] + spart[256 + tid] + spart[384 + tid];
        g_scores[blk * 128 + tid] = s + ba2[0];
    }
}

// ================================ K3 / K4 ========================================
__global__ void k3a_region_stats()
{
    __shared__ float red[256];
    const int r = blockIdx.x, tid = threadIdx.x;

    float mx = -1e30f;
    for (int m = tid; m < M_PER; m += 256)
        mx = fmaxf(mx, g_scores[m * R_REG + r]);
    red[tid] = mx; __syncthreads();
    for (int s = 128; s > 0; s >>= 1) {
        if (tid < s) red[tid] = fmaxf(red[tid], red[tid + s]);
        __syncthreads();
    }
    mx = red[0];
    __syncthreads();

    float sum = 0.f;
    for (int m = tid; m < M_PER; m += 256)
        sum += expf(g_scores[m * R_REG + r] - mx);
    red[tid] = sum; __syncthreads();
    for (int s = 128; s > 0; s >>= 1) {
        if (tid < s) red[tid] += red[tid + s];
        __syncthreads();
    }
    if (tid == 0) { g_rmax[r] = mx; g_rsum[r] = red[0]; }
}

__global__ void k3b_weighted_partial()
{
    const int s = blockIdx.x, r = blockIdx.y, tid = threadIdx.x;
    const float rmax = g_rmax[r];
    const int m0 = s * (M_PER / SPLITS);   // *64
    float a0 = 0.f, a1 = 0.f;
    #pragma unroll 4
    for (int mm = 0; mm < M_PER / SPLITS; mm++) {
        const int n = (m0 + mm) * R_REG + r;
        const float w = expf(g_scores[n] - rmax);
        const uint32_t* row = g_reP + (long)n * H_DIM;
        a0 += w * unpackf(row[tid]);
        a1 += w * unpackf(row[tid + 256]);
    }
    float* o = g_partial + (long)(r * SPLITS + s) * H_DIM;
    o[tid] = a0; o[tid + 256] = a1;
}

__global__ void k3c_reduce_rf()
{
    const int r = blockIdx.x, h = threadIdx.x;   // 512 threads
    float a = 0.f;
    for (int s = 0; s < SPLITS; s++)
        a += g_partial[(long)(r * SPLITS + s) * H_DIM + h];
    g_region_features[r * H_DIM + h] = a / g_rsum[r];
}

__global__ void k4a_slide_emb(const float* __restrict__ Ws, const float* __restrict__ bs)
{
    __shared__ float rf[H_DIM];
    const int r = blockIdx.x, h = threadIdx.x;   // 512 threads
    rf[h] = g_region_features[r * H_DIM + h];
    __syncthreads();
    float a = 0.f;
    #pragma unroll 4
    for (int k = 0; k < H_DIM; k++)
        a += rf[k] * Ws[k * H_DIM + h];
    g_slide_emb[r * H_DIM + h] = gelu_f(a + bs[h]);
}

__global__ void k4b_slide_attn(const float* __restrict__ Wsa1, const float* __restrict__ bsa1,
                               const float* __restrict__ Wsa2, const float* __restrict__ bsa2)
{
    __shared__ float se[H_DIM];
    __shared__ float red[256];
    const int r = blockIdx.x, j = threadIdx.x;   // 256 threads
    se[j] = g_slide_emb[r * H_DIM + j];
    se[j + 256] = g_slide_emb[r * H_DIM + j + 256];
    __syncthreads();
    float a = 0.f;
    #pragma unroll 4
    for (int h = 0; h < H_DIM; h++)
        a += se[h] * Wsa1[h * HH + j];
    red[j] = tanhf(a + bsa1[j]) * Wsa2[j];
    __syncthreads();
    for (int s = 128; s > 0; s >>= 1) {
        if (j < s) red[j] += red[j + s];
        __syncthreads();
    }
    if (j == 0) g_sa[r] = red[0] + bsa2[0];
}

__global__ void k4c_classify(const float* __restrict__ Wc1, const float* __restrict__ bc1,
                             const float* __restrict__ Wc2, const float* __restrict__ bc2,
                             float* __restrict__ out)
{
    __shared__ float w[R_REG];
    __shared__ float srep[H_DIM];
    __shared__ float c1s[HH];
    const int tid = threadIdx.x;   // 512 threads

    if (tid == 0) {
        float mx = g_sa[0];
        #pragma unroll
        for (int r = 1; r < R_REG; r++) mx = fmaxf(mx, g_sa[r]);
        float sum = 0.f;
        #pragma unroll
        for (int r = 0; r < R_REG; r++) { w[r] = expf(g_sa[r] - mx); sum += w[r]; }
        const float inv = 1.f / sum;
        #pragma unroll
        for (int r = 0; r < R_REG; r++) w[r] *= inv;
    }
    __syncthreads();

    {
        float a = 0.f;
        #pragma unroll
        for (int r = 0; r < R_REG; r++)
            a += w[r] * g_slide_emb[r * H_DIM + tid];
        srep[tid] = a;
    }
    __syncthreads();

    if (tid < HH) {
        float a = 0.f;
        #pragma unroll 4
        for (int h = 0; h < H_DIM; h++)
            a += srep[h] * Wc1[h * HH + tid];
        c1s[tid] = gelu_f(a + bc1[tid]);
    }
    __syncthreads();

    if (tid < 2) {
        float a = bc2[tid];
        #pragma unroll 4
        for (int j = 0; j < HH; j++)
            a += c1s[j] * Wc2[j * 2 + tid];
        out[tid] = a;
    }
}

// =================================================================================
extern "C" void kernel_launch(void* const* d_in, const int* in_sizes, int n_in,
                              void* d_out, int out_size)
{
    const float* emb  = (const float*)d_in[0];
    const float* W1   = (const float*)d_in[1];
    const float* b1   = (const float*)d_in[2];
    const float* Wa1  = (const float*)d_in[3];
    const float* ba1  = (const float*)d_in[4];
    const float* Wa2  = (const float*)d_in[5];
    const float* ba2  = (const float*)d_in[6];
    const float* Ws   = (const float*)d_in[7];
    const float* bs   = (const float*)d_in[8];
    const float* Wsa1 = (const float*)d_in[9];
    const float* bsa1 = (const float*)d_in[10];
    const float* Wsa2 = (const float*)d_in[11];
    const float* bsa2 = (const float*)d_in[12];
    const float* Wc1  = (const float*)d_in[13];
    const float* bc1  = (const float*)d_in[14];
    const float* Wc2  = (const float*)d_in[15];
    const float* bc2  = (const float*)d_in[16];
    float* out = (float*)d_out;

    kprep<<<(512 * 512 + 256 * 256 + 255) / 256, 256>>>(W1, Wa1);
    k1_mma<<<dim3(H_DIM / 128, N_TOK / 128), 512>>>(emb, b1);
    k2_mma<<<N_TOK / 128, 512>>>(ba1, Wa2, ba2);
    k3a_region_stats<<<R_REG, 256>>>();
    k3b_weighted_partial<<<dim3(SPLITS, R_REG), 256>>>();
    k3c_reduce_rf<<<R_REG, 512>>>();
    k4a_slide_emb<<<R_REG, 512>>>(Ws, bs);
    k4b_slide_attn<<<R_REG, 256>>>(Wsa1, bsa1, Wsa2, bsa2);
    k4c_classify<<<1, 512>>>(Wc1, bc1, Wc2, bc2, out);
}

// round 15
// speedup vs baseline: 1.4887x; 1.4887x over previous
#include <cuda_runtime.h>
#include <cuda_bf16.h>
#include <math.h>
#include <stdint.h>

// Problem constants
#define N_TOK 65536
#define D_IN  1024
#define H_DIM 512
#define HH    256          // H/2
#define R_REG 16
#define M_PER (N_TOK / R_REG)   // 4096
#define SPLITS 64

// ---------------- static device scratch (no allocations allowed) ----------------
__device__ float g_region_emb[N_TOK * H_DIM];            // 128 MiB
__device__ float g_scores[N_TOK];
__device__ float g_rmax[R_REG];
__device__ float g_rsum[R_REG];
__device__ float g_partial[R_REG * SPLITS * H_DIM];      // 2 MiB
__device__ float g_region_features[R_REG * H_DIM];
__device__ float g_slide_emb[R_REG * H_DIM];
__device__ float g_sa[R_REG];

__device__ __forceinline__ float gelu_f(float x) {
    // exact-erf GELU (matches torch nn.GELU default / jax approximate=False)
    return 0.5f * x * (1.0f + erff(x * 0.70710678118654752440f));
}

// ---------------- bf16 split helpers ----------------
__device__ __forceinline__ void split_bf(float x, uint32_t& h, uint32_t& l) {
    __nv_bfloat16 hb = __float2bfloat16_rn(x);
    float r = x - __bfloat162float(hb);   // exact in fp32
    __nv_bfloat16 lb = __float2bfloat16_rn(r);
    h = (uint32_t)(*(uint16_t*)&hb);
    l = (uint32_t)(*(uint16_t*)&lb);
}

// m16n8k16 bf16 MMA, f32 accumulate (sm_80+ mma.sync — valid on plain sm_103)
__device__ __forceinline__ void mma_bf16(float* d, const uint32_t* a, const uint32_t* b) {
    asm volatile(
        "mma.sync.aligned.m16n8k16.row.col.f32.bf16.bf16.f32 "
        "{%0,%1,%2,%3}, {%4,%5,%6,%7}, {%8,%9}, {%0,%1,%2,%3};"
        : "+f"(d[0]), "+f"(d[1]), "+f"(d[2]), "+f"(d[3])
        : "r"(a[0]), "r"(a[1]), "r"(a[2]), "r"(a[3]), "r"(b[0]), "r"(b[1]));
}

// =================================================================================
// K1 (mma.sync bf16-split): region_emb = gelu(E @ W1 + b1)       [R12-proven]
// CTA tile 128x128, BK=16, 512 threads = 16 warps 4(m)x4(n), warp tile 32x32.
// 3 MMAs (hh, hl, lh) per tile. 48B-stride planes: conflict-free fragment LDS.
// =================================================================================
#define K1_AH 0
#define K1_AL 6144
#define K1_BH 12288
#define K1_BL 18432
#define K1_SMEM 24576

__global__ __launch_bounds__(512, 1)
void k1_mma(const float* __restrict__ A, const float* __restrict__ W,
            const float* __restrict__ bias)
{
    __shared__ __align__(16) unsigned char sm[K1_SMEM];

    const int tid = threadIdx.x;
    const int wid = tid >> 5;
    const int lane = tid & 31;
    const int g = lane >> 2;
    const int t = lane & 3;
    const int bx = blockIdx.x;     // N block: 0..3
    const int by = blockIdx.y;     // M block: 0..511

    const int warp_m = (wid & 3) * 32;
    const int warp_n = (wid >> 2) * 32;

    const int a_row = tid >> 2;
    const int a_q   = tid & 3;
    const float* Ag = A + (long)(by * 128 + a_row) * D_IN + a_q * 4;
    const int b_k0 = (tid >> 6) * 2;
    const int b_n  = tid & 63;

    const uint32_t* AH = (const uint32_t*)(sm + K1_AH);
    const uint32_t* AL = (const uint32_t*)(sm + K1_AL);
    const uint32_t* BH = (const uint32_t*)(sm + K1_BH);
    const uint32_t* BL = (const uint32_t*)(sm + K1_BL);

    float acc[2][4][4];
    #pragma unroll
    for (int mt = 0; mt < 2; mt++)
        #pragma unroll
        for (int nt = 0; nt < 4; nt++)
            #pragma unroll
            for (int r = 0; r < 4; r++) acc[mt][nt][r] = 0.f;

    float4 pa = *(const float4*)Ag;
    float pB[2][2];
    #pragma unroll
    for (int nj = 0; nj < 2; nj++) {
        const float* wp = W + (long)b_k0 * H_DIM + bx * 128 + b_n + 64 * nj;
        pB[nj][0] = wp[0];
        pB[nj][1] = wp[H_DIM];
    }

    for (int c = 0; c < D_IN / 16; c++) {
        {
            uint32_t h0, h1, h2, h3, l0, l1, l2, l3;
            split_bf(pa.x, h0, l0); split_bf(pa.y, h1, l1);
            split_bf(pa.z, h2, l2); split_bf(pa.w, h3, l3);
            *(uint2*)(sm + K1_AH + a_row * 48 + a_q * 8) = make_uint2(h0 | (h1 << 16), h2 | (h3 << 16));
            *(uint2*)(sm + K1_AL + a_row * 48 + a_q * 8) = make_uint2(l0 | (l1 << 16), l2 | (l3 << 16));
            #pragma unroll
            for (int nj = 0; nj < 2; nj++) {
                uint32_t bh0, bl0, bh1, bl1;
                split_bf(pB[nj][0], bh0, bl0);
                split_bf(pB[nj][1], bh1, bl1);
                const int n = b_n + 64 * nj;
                *(uint32_t*)(sm + K1_BH + n * 48 + b_k0 * 2) = bh0 | (bh1 << 16);
                *(uint32_t*)(sm + K1_BL + n * 48 + b_k0 * 2) = bl0 | (bl1 << 16);
            }
        }
        __syncthreads();

        if (c + 1 < D_IN / 16) {
            pa = *(const float4*)(Ag + (c + 1) * 16);
            #pragma unroll
            for (int nj = 0; nj < 2; nj++) {
                const float* wp = W + (long)((c + 1) * 16 + b_k0) * H_DIM + bx * 128 + b_n + 64 * nj;
                pB[nj][0] = wp[0];
                pB[nj][1] = wp[H_DIM];
            }
        }

        uint32_t ah[2][4], al_[2][4];
        #pragma unroll
        for (int mt = 0; mt < 2; mt++) {
            const int r0 = (warp_m + mt * 16 + g) * 12 + t;
            ah[mt][0]  = AH[r0];       ah[mt][1]  = AH[r0 + 96];
            ah[mt][2]  = AH[r0 + 4];   ah[mt][3]  = AH[r0 + 100];
            al_[mt][0] = AL[r0];       al_[mt][1] = AL[r0 + 96];
            al_[mt][2] = AL[r0 + 4];   al_[mt][3] = AL[r0 + 100];
        }
        uint32_t bh[4][2], bl[4][2];
        #pragma unroll
        for (int nt = 0; nt < 4; nt++) {
            const int q0 = (warp_n + nt * 8 + g) * 12 + t;
            bh[nt][0] = BH[q0]; bh[nt][1] = BH[q0 + 4];
            bl[nt][0] = BL[q0]; bl[nt][1] = BL[q0 + 4];
        }
        #pragma unroll
        for (int mt = 0; mt < 2; mt++)
            #pragma unroll
            for (int nt = 0; nt < 4; nt++) {
                mma_bf16(acc[mt][nt], ah[mt],  bh[nt]);
                mma_bf16(acc[mt][nt], ah[mt],  bl[nt]);
                mma_bf16(acc[mt][nt], al_[mt], bh[nt]);
            }
        __syncthreads();
    }

    #pragma unroll
    for (int mt = 0; mt < 2; mt++) {
        const int row0 = by * 128 + warp_m + mt * 16 + g;
        #pragma unroll
        for (int nt = 0; nt < 4; nt++) {
            const int col = bx * 128 + warp_n + nt * 8 + 2 * t;
            const float2 bb = *(const float2*)(bias + col);
            const float* d = acc[mt][nt];
            float2 v0, v1;
            v0.x = gelu_f(d[0] + bb.x); v0.y = gelu_f(d[1] + bb.y);
            v1.x = gelu_f(d[2] + bb.x); v1.y = gelu_f(d[3] + bb.y);
            *(float2*)(g_region_emb + (long)row0 * H_DIM + col) = v0;
            *(float2*)(g_region_emb + (long)(row0 + 8) * H_DIM + col) = v1;
        }
    }
}

// =================================================================================
// K2 (mma.sync bf16-split, register-safe): scores = tanh(re @ Wa1 + ba1) @ Wa2 + ba2
// CTA tile 64x256 (FULL Wa1 width -> tanh+Wa2 contraction fused in epilogue),
// BK=16, 512 threads = 16 warps laid out 2(m) x 8(n), warp tile 32x32
// -> acc[2][4][4] = 32 regs/thread (same proven budget as k1; no spills).
// A = region_emb fp32 (split in-kernel), B = Wa1 fp32 (split in-kernel).
// Same 48B-stride planes + fragment maps as k1.
// =================================================================================
#define K2_AH 0
#define K2_AL 3072
#define K2_BH 6144
#define K2_BL 18432
#define K2_SP 30720
#define K2_SMEM 32768

__global__ __launch_bounds__(512, 1)
void k2_mma(const float* __restrict__ Wa1, const float* __restrict__ ba1,
            const float* __restrict__ Wa2, const float* __restrict__ ba2)
{
    __shared__ __align__(16) unsigned char sm[K2_SMEM];

    const int tid = threadIdx.x;
    const int wid = tid >> 5;
    const int lane = tid & 31;
    const int g = lane >> 2;
    const int t = lane & 3;
    const int blk = blockIdx.x;    // token block 0..1023 (64 tokens each)

    const int warp_m = (wid & 1) * 32;     // 0,32
    const int warp_n = (wid >> 1) * 32;    // 0..224

    // A: 64 rows x 16 k = 1024 floats; 1 float2 (one k-pair) per thread
    const int a_row = tid >> 3;            // 0..63
    const int a_q   = tid & 7;             // k-pair index 0..7
    const float* Ag = g_region_emb + (long)(blk * 64 + a_row) * H_DIM + a_q * 2;
    // B: 16 k x 256 n; thread covers k-pair b_k0 for 4 n's (n = b_n + 64*nj)
    const int b_k0 = (tid >> 6) * 2;       // 0,2,...,14
    const int b_n  = tid & 63;

    const uint32_t* AH = (const uint32_t*)(sm + K2_AH);
    const uint32_t* AL = (const uint32_t*)(sm + K2_AL);
    const uint32_t* BH = (const uint32_t*)(sm + K2_BH);
    const uint32_t* BL = (const uint32_t*)(sm + K2_BL);

    float acc[2][4][4];
    #pragma unroll
    for (int mt = 0; mt < 2; mt++)
        #pragma unroll
        for (int nt = 0; nt < 4; nt++)
            #pragma unroll
            for (int r = 0; r < 4; r++) acc[mt][nt][r] = 0.f;

    // initial prefetch (chunk 0)
    float2 pa = *(const float2*)Ag;
    float pB[4][2];
    #pragma unroll
    for (int nj = 0; nj < 4; nj++) {
        const float* wp = Wa1 + (long)b_k0 * HH + b_n + 64 * nj;
        pB[nj][0] = wp[0];
        pB[nj][1] = wp[HH];
    }

    for (int c = 0; c < H_DIM / 16; c++) {
        // ---- store chunk into split planes ----
        {
            uint32_t h0, h1, l0, l1;
            split_bf(pa.x, h0, l0); split_bf(pa.y, h1, l1);
            *(uint32_t*)(sm + K2_AH + a_row * 48 + a_q * 4) = h0 | (h1 << 16);
            *(uint32_t*)(sm + K2_AL + a_row * 48 + a_q * 4) = l0 | (l1 << 16);
            #pragma unroll
            for (int nj = 0; nj < 4; nj++) {
                uint32_t bh0, bl0, bh1, bl1;
                split_bf(pB[nj][0], bh0, bl0);
                split_bf(pB[nj][1], bh1, bl1);
                const int n = b_n + 64 * nj;
                *(uint32_t*)(sm + K2_BH + n * 48 + b_k0 * 2) = bh0 | (bh1 << 16);
                *(uint32_t*)(sm + K2_BL + n * 48 + b_k0 * 2) = bl0 | (bl1 << 16);
            }
        }
        __syncthreads();

        // ---- prefetch next chunk ----
        if (c + 1 < H_DIM / 16) {
            pa = *(const float2*)(Ag + (c + 1) * 16);
            #pragma unroll
            for (int nj = 0; nj < 4; nj++) {
                const float* wp = Wa1 + (long)((c + 1) * 16 + b_k0) * HH + b_n + 64 * nj;
                pB[nj][0] = wp[0];
                pB[nj][1] = wp[HH];
            }
        }

        // ---- fragments + 3-term MMA ----
        uint32_t ah[2][4], al_[2][4];
        #pragma unroll
        for (int mt = 0; mt < 2; mt++) {
            const int r0 = (warp_m + mt * 16 + g) * 12 + t;
            ah[mt][0]  = AH[r0];       ah[mt][1]  = AH[r0 + 96];
            ah[mt][2]  = AH[r0 + 4];   ah[mt][3]  = AH[r0 + 100];
            al_[mt][0] = AL[r0];       al_[mt][1] = AL[r0 + 96];
            al_[mt][2] = AL[r0 + 4];   al_[mt][3] = AL[r0 + 100];
        }
        uint32_t bh[4][2], bl[4][2];
        #pragma unroll
        for (int nt = 0; nt < 4; nt++) {
            const int q0 = (warp_n + nt * 8 + g) * 12 + t;
            bh[nt][0] = BH[q0]; bh[nt][1] = BH[q0 + 4];
            bl[nt][0] = BL[q0]; bl[nt][1] = BL[q0 + 4];
        }
        #pragma unroll
        for (int mt = 0; mt < 2; mt++)
            #pragma unroll
            for (int nt = 0; nt < 4; nt++) {
                mma_bf16(acc[mt][nt], ah[mt],  bh[nt]);
                mma_bf16(acc[mt][nt], ah[mt],  bl[nt]);
                mma_bf16(acc[mt][nt], al_[mt], bh[nt]);
            }
        __syncthreads();
    }

    // ---- epilogue: tanh * Wa2 contraction, quad-shfl + 8-group smem reduce ----
    float* spart = (float*)(sm + K2_SP);   // [8 n-groups][64 rows]
    const int ng = wid >> 1;
    #pragma unroll
    for (int mt = 0; mt < 2; mt++) {
        float s0 = 0.f, s1 = 0.f;
        #pragma unroll
        for (int nt = 0; nt < 4; nt++) {
            const int col = warp_n + nt * 8 + 2 * t;
            const float2 bb = *(const float2*)(ba1 + col);
            const float2 ww = *(const float2*)(Wa2 + col);
            const float* d = acc[mt][nt];
            s0 += tanhf(d[0] + bb.x) * ww.x + tanhf(d[1] + bb.y) * ww.y;
            s1 += tanhf(d[2] + bb.x) * ww.x + tanhf(d[3] + bb.y) * ww.y;
        }
        s0 += __shfl_down_sync(0xffffffffu, s0, 2, 4);
        s0 += __shfl_down_sync(0xffffffffu, s0, 1, 4);
        s1 += __shfl_down_sync(0xffffffffu, s1, 2, 4);
        s1 += __shfl_down_sync(0xffffffffu, s1, 1, 4);
        if (t == 0) {
            spart[ng * 64 + warp_m + mt * 16 + g]     = s0;
            spart[ng * 64 + warp_m + mt * 16 + g + 8] = s1;
        }
    }
    __syncthreads();
    if (tid < 64) {
        float s = 0.f;
        #pragma unroll
        for (int i = 0; i < 8; i++) s += spart[i * 64 + tid];
        g_scores[blk * 64 + tid] = s + ba2[0];
    }
}

// ================================ K3 / K4 (R12 verbatim) =========================
__global__ void k3a_region_stats()
{
    __shared__ float red[256];
    const int r = blockIdx.x, tid = threadIdx.x;

    float mx = -1e30f;
    for (int m = tid; m < M_PER; m += 256)
        mx = fmaxf(mx, g_scores[m * R_REG + r]);
    red[tid] = mx; __syncthreads();
    for (int s = 128; s > 0; s >>= 1) {
        if (tid < s) red[tid] = fmaxf(red[tid], red[tid + s]);
        __syncthreads();
    }
    mx = red[0];
    __syncthreads();

    float sum = 0.f;
    for (int m = tid; m < M_PER; m += 256)
        sum += expf(g_scores[m * R_REG + r] - mx);
    red[tid] = sum; __syncthreads();
    for (int s = 128; s > 0; s >>= 1) {
        if (tid < s) red[tid] += red[tid + s];
        __syncthreads();
    }
    if (tid == 0) { g_rmax[r] = mx; g_rsum[r] = red[0]; }
}

__global__ void k3b_weighted_partial()
{
    const int s = blockIdx.x, r = blockIdx.y, tid = threadIdx.x;
    const float rmax = g_rmax[r];
    const int m0 = s * (M_PER / SPLITS);   // *64
    float a0 = 0.f, a1 = 0.f;
    #pragma unroll 4
    for (int mm = 0; mm < M_PER / SPLITS; mm++) {
        const int n = (m0 + mm) * R_REG + r;
        const float w = expf(g_scores[n] - rmax);
        const float* row = g_region_emb + (long)n * H_DIM;
        a0 += w * row[tid];
        a1 += w * row[tid + 256];
    }
    float* o = g_partial + (long)(r * SPLITS + s) * H_DIM;
    o[tid] = a0; o[tid + 256] = a1;
}

__global__ void k3c_reduce_rf()
{
    const int r = blockIdx.x, h = threadIdx.x;   // 512 threads
    float a = 0.f;
    for (int s = 0; s < SPLITS; s++)
        a += g_partial[(long)(r * SPLITS + s) * H_DIM + h];
    g_region_features[r * H_DIM + h] = a / g_rsum[r];
}

__global__ void k4a_slide_emb(const float* __restrict__ Ws, const float* __restrict__ bs)
{
    __shared__ float rf[H_DIM];
    const int r = blockIdx.x, h = threadIdx.x;   // 512 threads
    rf[h] = g_region_features[r * H_DIM + h];
    __syncthreads();
    float a = 0.f;
    #pragma unroll 4
    for (int k = 0; k < H_DIM; k++)
        a += rf[k] * Ws[k * H_DIM + h];
    g_slide_emb[r * H_DIM + h] = gelu_f(a + bs[h]);
}

__global__ void k4b_slide_attn(const float* __restrict__ Wsa1, const float* __restrict__ bsa1,
                               const float* __restrict__ Wsa2, const float* __restrict__ bsa2)
{
    __shared__ float se[H_DIM];
    __shared__ float red[256];
    const int r = blockIdx.x, j = threadIdx.x;   // 256 threads
    se[j] = g_slide_emb[r * H_DIM + j];
    se[j + 256] = g_slide_emb[r * H_DIM + j + 256];
    __syncthreads();
    float a = 0.f;
    #pragma unroll 4
    for (int h = 0; h < H_DIM; h++)
        a += se[h] * Wsa1[h * HH + j];
    red[j] = tanhf(a + bsa1[j]) * Wsa2[j];
    __syncthreads();
    for (int s = 128; s > 0; s >>= 1) {
        if (j < s) red[j] += red[j + s];
        __syncthreads();
    }
    if (j == 0) g_sa[r] = red[0] + bsa2[0];
}

__global__ void k4c_classify(const float* __restrict__ Wc1, const float* __restrict__ bc1,
                             const float* __restrict__ Wc2, const float* __restrict__ bc2,
                             float* __restrict__ out)
{
    __shared__ float w[R_REG];
    __shared__ float srep[H_DIM];
    __shared__ float c1s[HH];
    const int tid = threadIdx.x;   // 512 threads

    if (tid == 0) {
        float mx = g_sa[0];
        #pragma unroll
        for (int r = 1; r < R_REG; r++) mx = fmaxf(mx, g_sa[r]);
        float sum = 0.f;
        #pragma unroll
        for (int r = 0; r < R_REG; r++) { w[r] = expf(g_sa[r] - mx); sum += w[r]; }
        const float inv = 1.f / sum;
        #pragma unroll
        for (int r = 0; r < R_REG; r++) w[r] *= inv;
    }
    __syncthreads();

    {
        float a = 0.f;
        #pragma unroll
        for (int r = 0; r < R_REG; r++)
            a += w[r] * g_slide_emb[r * H_DIM + tid];
        srep[tid] = a;
    }
    __syncthreads();

    if (tid < HH) {
        float a = 0.f;
        #pragma unroll 4
        for (int h = 0; h < H_DIM; h++)
            a += srep[h] * Wc1[h * HH + tid];
        c1s[tid] = gelu_f(a + bc1[tid]);
    }
    __syncthreads();

    if (tid < 2) {
        float a = bc2[tid];
        #pragma unroll 4
        for (int j = 0; j < HH; j++)
            a += c1s[j] * Wc2[j * 2 + tid];
        out[tid] = a;
    }
}

// =================================================================================
extern "C" void kernel_launch(void* const* d_in, const int* in_sizes, int n_in,
                              void* d_out, int out_size)
{
    const float* emb  = (const float*)d_in[0];
    const float* W1   = (const float*)d_in[1];
    const float* b1   = (const float*)d_in[2];
    const float* Wa1  = (const float*)d_in[3];
    const float* ba1  = (const float*)d_in[4];
    const float* Wa2  = (const float*)d_in[5];
    const float* ba2  = (const float*)d_in[6];
    const float* Ws   = (const float*)d_in[7];
    const float* bs   = (const float*)d_in[8];
    const float* Wsa1 = (const float*)d_in[9];
    const float* bsa1 = (const float*)d_in[10];
    const float* Wsa2 = (const float*)d_in[11];
    const float* bsa2 = (const float*)d_in[12];
    const float* Wc1  = (const float*)d_in[13];
    const float* bc1  = (const float*)d_in[14];
    const float* Wc2  = (const float*)d_in[15];
    const float* bc2  = (const float*)d_in[16];
    float* out = (float*)d_out;

    k1_mma<<<dim3(H_DIM / 128, N_TOK / 128), 512>>>(emb, W1, b1);
    k2_mma<<<N_TOK / 64, 512>>>(Wa1, ba1, Wa2, ba2);
    k3a_region_stats<<<R_REG, 256>>>();
    k3b_weighted_partial<<<dim3(SPLITS, R_REG), 256>>>();
    k3c_reduce_rf<<<R_REG, 512>>>();
    k4a_slide_emb<<<R_REG, 512>>>(Ws, bs);
    k4b_slide_attn<<<R_REG, 256>>>(Wsa1, bsa1, Wsa2, bsa2);
    k4c_classify<<<1, 512>>>(Wc1, bc1, Wc2, bc2, out);
}